// round 15
// baseline (speedup 1.0000x reference)
#include <cuda_runtime.h>
#include <cuda_bf16.h>
#include <math.h>
#include <stdint.h>

// Problem constants
#define B_   4
#define LV   2048
#define LE   64
#define LT   2112      // LV + LE
#define D_   960
#define H_   15
#define KVH_ 5
#define HD_  64
#define NKV  320       // KVH_*HD_

// Scratch (device globals; bf16 activations)
__device__ __nv_bfloat16 g_xn[B_*LT*D_];
__device__ __nv_bfloat16 g_q [B_*LT*D_];
__device__ __nv_bfloat16 g_k [B_*LT*NKV];
__device__ __nv_bfloat16 g_v [B_*LT*NKV];
__device__ __nv_bfloat16 g_at[B_*LT*D_];
// bf16 transposed weights [n][k], k stride 960
__device__ __nv_bfloat16 g_wq_v[960*960];
__device__ __nv_bfloat16 g_wk_v[320*960];
__device__ __nv_bfloat16 g_wv_v[320*960];
__device__ __nv_bfloat16 g_wo_v[960*960];
__device__ __nv_bfloat16 g_wq_e[960*960];
__device__ __nv_bfloat16 g_wk_e[320*960];
__device__ __nv_bfloat16 g_wv_e[320*960];
__device__ __nv_bfloat16 g_wo_e[960*960];

// ---------------------------------------------------------------------------
// helpers
// ---------------------------------------------------------------------------
__device__ __forceinline__ uint32_t pack2(float lo, float hi) {
    __nv_bfloat162 h = __floats2bfloat162_rn(lo, hi);
    return *(uint32_t*)&h;
}
__device__ __forceinline__ void mma16(float* c, const uint32_t* a, uint32_t b0, uint32_t b1) {
    asm("mma.sync.aligned.m16n8k16.row.col.f32.bf16.bf16.f32 "
        "{%0,%1,%2,%3}, {%4,%5,%6,%7}, {%8,%9}, {%0,%1,%2,%3};"
        : "+f"(c[0]), "+f"(c[1]), "+f"(c[2]), "+f"(c[3])
        : "r"(a[0]), "r"(a[1]), "r"(a[2]), "r"(a[3]), "r"(b0), "r"(b1));
}
__device__ __forceinline__ void ldsm4(uint32_t* r, const __nv_bfloat16* p) {
    uint32_t a = (uint32_t)__cvta_generic_to_shared(p);
    asm volatile("ldmatrix.sync.aligned.m8n8.x4.shared.b16 {%0,%1,%2,%3}, [%4];"
        : "=r"(r[0]), "=r"(r[1]), "=r"(r[2]), "=r"(r[3]) : "r"(a));
}
__device__ __forceinline__ void ldsm4t(uint32_t* r, const __nv_bfloat16* p) {
    uint32_t a = (uint32_t)__cvta_generic_to_shared(p);
    asm volatile("ldmatrix.sync.aligned.m8n8.x4.trans.shared.b16 {%0,%1,%2,%3}, [%4];"
        : "=r"(r[0]), "=r"(r[1]), "=r"(r[2]), "=r"(r[3]) : "r"(a));
}
__device__ __forceinline__ void cp16(__nv_bfloat16* smem, const __nv_bfloat16* gmem) {
    uint32_t a = (uint32_t)__cvta_generic_to_shared(smem);
    asm volatile("cp.async.cg.shared.global [%0], [%1], 16;" :: "r"(a), "l"(gmem));
}
__device__ __forceinline__ void cp_commit() { asm volatile("cp.async.commit_group;"); }
__device__ __forceinline__ void cp_wait0()  { asm volatile("cp.async.wait_group 0;"); }
__device__ __forceinline__ void cp_wait1()  { asm volatile("cp.async.wait_group 1;"); }
__device__ __forceinline__ void cp_wait2()  { asm volatile("cp.async.wait_group 2;"); }

// ---------------------------------------------------------------------------
// Fused prep: weight convert+transpose (blocks [0,7200)) + rmsnorm (rest).
// Block = 256 threads. Grid.x = 7200 + B_*LT.
// ---------------------------------------------------------------------------
__global__ void __launch_bounds__(256) prep_kernel(
    const float* hv, const float* he, const float* lnv, const float* lne,
    const float* w0, const float* w1, const float* w2, const float* w3,
    const float* w4, const float* w5, const float* w6, const float* w7)
{
    __shared__ float sm[32*33];
    int bid = blockIdx.x;
    int tid = threadIdx.x;

    if (bid < 7200) {
        // ---- weight convert + transpose ----
        int sel = bid / 900;
        int rr  = bid % 900;
        const float* W; __nv_bfloat16* Wt; int N;
        if      (sel == 0) { W = w0; Wt = g_wq_v; N = 960; }
        else if (sel == 1) { W = w1; Wt = g_wk_v; N = 320; }
        else if (sel == 2) { W = w2; Wt = g_wv_v; N = 320; }
        else if (sel == 3) { W = w3; Wt = g_wo_v; N = 960; }
        else if (sel == 4) { W = w4; Wt = g_wq_e; N = 960; }
        else if (sel == 5) { W = w5; Wt = g_wk_e; N = 320; }
        else if (sel == 6) { W = w6; Wt = g_wv_e; N = 320; }
        else               { W = w7; Wt = g_wo_e; N = 960; }
        int n0 = (rr % 30) * 32, k0 = (rr / 30) * 32;
        if (n0 >= N) return;
        int x = tid & 31, y = tid >> 5;
        #pragma unroll
        for (int i = 0; i < 32; i += 8)
            sm[(y+i)*33 + x] = W[(size_t)(k0+y+i)*N + n0 + x];
        __syncthreads();
        #pragma unroll
        for (int i = 0; i < 32; i += 8)
            Wt[(size_t)(n0+y+i)*960 + k0 + x] = __float2bfloat16(sm[x*33 + y+i]);
    } else {
        // ---- rmsnorm ----
        int r = bid - 7200;
        int b = r / LT, l = r % LT;
        const float* src; const float* w;
        if (l < LV) { src = hv + ((size_t)b*LV + l)*D_; w = lnv; }
        else        { src = he + ((size_t)b*LE + (l-LV))*D_; w = lne; }
        float4 x = make_float4(0.f,0.f,0.f,0.f);
        if (tid < 240) x = ((const float4*)src)[tid];
        float ss = x.x*x.x + x.y*x.y + x.z*x.z + x.w*x.w;
        #pragma unroll
        for (int o = 16; o > 0; o >>= 1) ss += __shfl_xor_sync(0xffffffffu, ss, o);
        if ((tid & 31) == 0) sm[tid >> 5] = ss;
        __syncthreads();
        float tot = 0.f;
        #pragma unroll
        for (int i = 0; i < 8; i++) tot += sm[i];
        float inv = rsqrtf(tot * (1.0f/D_) + 1e-6f);
        if (tid < 240) {
            float4 wv = ((const float4*)w)[tid];
            uint2 o;
            o.x = pack2(x.x*inv*wv.x, x.y*inv*wv.y);
            o.y = pack2(x.z*inv*wv.z, x.w*inv*wv.w);
            ((uint2*)(g_xn + (size_t)r * D_))[tid] = o;
        }
    }
}

// ---------------------------------------------------------------------------
// Fused bf16 GEMM, 3-stage cp.async ring, ONE syncthreads per k-iter.
// MODE 0: QKV. grid (25, 17, 4). MODE 1: O-proj. grid (15, 17, 4).
// Tile M=128, N=64, Ktile=32, 30 k-tiles. 8 warps (4m x 2n), 32x32/warp.
// ---------------------------------------------------------------------------
#define TS 40
#define NKT_GEMM 30

template<int MODE>
__global__ void __launch_bounds__(256) fgemm(
    float* __restrict__ Out, const float* __restrict__ Rv, const float* __restrict__ Re)
{
    __shared__ __align__(16) __nv_bfloat16 As[3][128*TS];
    __shared__ __align__(16) __nv_bfloat16 Ws[3][64*TS];

    int nx = blockIdx.x;
    int my = blockIdx.y;
    int b  = blockIdx.z;
    bool is_exp = (my == 16);
    int row0   = is_exp ? 2048 : 0;
    int mb     = is_exp ? 0    : my*128;
    int mvalid = is_exp ? 64   : 2048;

    const __nv_bfloat16* A;
    const __nv_bfloat16* Wt;
    __nv_bfloat16* Cb = nullptr;
    const float* R = nullptr;
    int N, n0, Rrows = 0;
    if (MODE == 0) {
        A = g_xn;
        if (nx < 15)      { Wt = is_exp ? g_wq_e : g_wq_v; Cb = g_q; N = 960; n0 = nx*64; }
        else if (nx < 20) { Wt = is_exp ? g_wk_e : g_wk_v; Cb = g_k; N = 320; n0 = (nx-15)*64; }
        else              { Wt = is_exp ? g_wv_e : g_wv_v; Cb = g_v; N = 320; n0 = (nx-20)*64; }
    } else {
        A = g_at;
        Wt = is_exp ? g_wo_e : g_wo_v;
        R  = is_exp ? Re : Rv;
        Rrows = is_exp ? 64 : 2048;
        N = 960; n0 = nx*64;
    }

    int tid  = threadIdx.x;
    int wid  = tid >> 5, lane = tid & 31;
    int g = lane >> 2, t = lane & 3;
    int wm = wid >> 1, wn = wid & 1;
    int lr = lane & 7, lb1 = (lane >> 3) & 1, lb2 = lane >> 4;

    // per-thread load coords (hoisted)
    int am0 = tid >> 2,        aseg0 = (tid & 3);
    int am1 = (tid+256) >> 2,  aseg1 = ((tid+256) & 3);
    int rl0 = mb + am0; if (rl0 >= mvalid) rl0 = mvalid - 1;
    int rl1 = mb + am1; if (rl1 >= mvalid) rl1 = mvalid - 1;
    const __nv_bfloat16* a_src0 = A + ((size_t)(b*LT + row0 + rl0))*D_ + aseg0*8;
    const __nv_bfloat16* a_src1 = A + ((size_t)(b*LT + row0 + rl1))*D_ + aseg1*8;
    int wn_ = tid >> 2, wseg = tid & 3;
    const __nv_bfloat16* w_src = Wt + (size_t)(n0 + wn_)*960 + wseg*8;

    float acc[2][4][4] = {};

    // prologue: prefetch stages 0 and 1
    {
        cp16(&As[0][am0*TS + aseg0*8], a_src0);
        cp16(&As[0][am1*TS + aseg1*8], a_src1);
        cp16(&Ws[0][wn_*TS + wseg*8], w_src);
        cp_commit();
        cp16(&As[1][am0*TS + aseg0*8], a_src0 + 32);
        cp16(&As[1][am1*TS + aseg1*8], a_src1 + 32);
        cp16(&Ws[1][wn_*TS + wseg*8], w_src + 32);
        cp_commit();
    }

    int s = 0;       // stage of iteration it
    int ps = 2;      // stage to prefetch (it+2)
    for (int it = 0; it < NKT_GEMM; it++) {
        if (it < NKT_GEMM - 2) cp_wait1(); else cp_wait0();
        __syncthreads();
        if (it + 2 < NKT_GEMM) {
            int k0 = (it+2)*32;
            cp16(&As[ps][am0*TS + aseg0*8], a_src0 + k0);
            cp16(&As[ps][am1*TS + aseg1*8], a_src1 + k0);
            cp16(&Ws[ps][wn_*TS + wseg*8], w_src + k0);
            cp_commit();
        }

        #pragma unroll
        for (int ks = 0; ks < 2; ks++) {
            int kb = ks*16;
            uint32_t a[2][4];
            #pragma unroll
            for (int mt = 0; mt < 2; mt++)
                ldsm4(a[mt], &As[s][(wm*32 + mt*16 + lr + lb1*8)*TS + kb + lb2*8]);
            #pragma unroll
            for (int ntp = 0; ntp < 2; ntp++) {
                uint32_t bq[4];
                ldsm4(bq, &Ws[s][(wn*32 + ntp*16 + lr + lb2*8)*TS + kb + lb1*8]);
                #pragma unroll
                for (int mt = 0; mt < 2; mt++) {
                    mma16(acc[mt][2*ntp  ], a[mt], bq[0], bq[1]);
                    mma16(acc[mt][2*ntp+1], a[mt], bq[2], bq[3]);
                }
            }
        }
        s  = (s  == 2) ? 0 : s + 1;
        ps = (ps == 2) ? 0 : ps + 1;
    }

    #pragma unroll
    for (int mt = 0; mt < 2; mt++) {
        #pragma unroll
        for (int nt = 0; nt < 4; nt++) {
            int col = n0 + wn*32 + nt*8 + 2*t;
            int m0r = mb + wm*32 + mt*16 + g;
            int m1r = m0r + 8;
            if (MODE == 1) {
                if (m0r < mvalid) {
                    float2 rv = *(const float2*)(R + ((size_t)b*Rrows + m0r)*D_ + col);
                    float2 o = make_float2(acc[mt][nt][0] + rv.x, acc[mt][nt][1] + rv.y);
                    *(float2*)(Out + ((size_t)(b*LT + row0 + m0r))*D_ + col) = o;
                }
                if (m1r < mvalid) {
                    float2 rv = *(const float2*)(R + ((size_t)b*Rrows + m1r)*D_ + col);
                    float2 o = make_float2(acc[mt][nt][2] + rv.x, acc[mt][nt][3] + rv.y);
                    *(float2*)(Out + ((size_t)(b*LT + row0 + m1r))*D_ + col) = o;
                }
            } else {
                if (m0r < mvalid)
                    *(uint32_t*)&Cb[((size_t)(b*LT + row0 + m0r))*N + col] =
                        pack2(acc[mt][nt][0], acc[mt][nt][1]);
                if (m1r < mvalid)
                    *(uint32_t*)&Cb[((size_t)(b*LT + row0 + m1r))*N + col] =
                        pack2(acc[mt][nt][2], acc[mt][nt][3]);
            }
        }
    }
}

// ---------------------------------------------------------------------------
// RoPE v2: ONE warp per row, sincos computed ONCE, looped over all 20 heads.
// Q gets scale 0.125*log2(e) (softmax runs in log2 space); K gets 1.0.
// ---------------------------------------------------------------------------
__global__ void __launch_bounds__(256) rope_kernel(
    const int* __restrict__ pos_v, const int* __restrict__ pos_e)
{
    int row  = blockIdx.x * 8 + (threadIdx.x >> 5);
    int lane = threadIdx.x & 31;
    int b = row / LT, l = row % LT;
    int p = (l < LV) ? pos_v[b*LV + l] : pos_e[b*LE + (l - LV)];
    float invts = exp2f((float)lane * -0.41524101186407974f);
    float rad = (float)p * invts;
    float kk = rintf(rad * 0.15915494309189535f);
    float r  = fmaf(-kk, 6.28125f, rad);
    r = fmaf(-kk, 0.0019353071795864769f, r);
    float sn, cs;
    __sincosf(r, &sn, &cs);

    const float QSC = 0.125f * 1.4426950408889634f;
    __nv_bfloat16* qbase = g_q + (size_t)row*D_;
    #pragma unroll
    for (int hh = 0; hh < H_; hh++) {
        __nv_bfloat16* base = qbase + hh*HD_;
        float x1 = __bfloat162float(base[lane]);
        float x2 = __bfloat162float(base[lane + 32]);
        base[lane]      = __float2bfloat16((x1*cs - x2*sn) * QSC);
        base[lane + 32] = __float2bfloat16((x2*cs + x1*sn) * QSC);
    }
    __nv_bfloat16* kbase = g_k + (size_t)row*NKV;
    #pragma unroll
    for (int hh = 0; hh < KVH_; hh++) {
        __nv_bfloat16* base = kbase + hh*HD_;
        float x1 = __bfloat162float(base[lane]);
        float x2 = __bfloat162float(base[lane + 32]);
        base[lane]      = __float2bfloat16(x1*cs - x2*sn);
        base[lane + 32] = __float2bfloat16(x2*cs + x1*sn);
    }
}

// ---------------------------------------------------------------------------
// bf16 flash attention. Split K/V commit groups: S-phase waits only for K;
// V-wait deferred until after softmax (softmax touches no smem).
// 2 barriers/iter (same as proven structure); wait_group cannot deadlock.
// Tile 128q x 64k, 8 warps x 16 q rows. K,V natural [key][d], stride 72 halfs.
// Grid (17, 15, 4); qt 16 = expert rows (causal over expert keys).
// ---------------------------------------------------------------------------
#define KS 72

__global__ void __launch_bounds__(256) attn_tc()
{
    __shared__ __align__(16) __nv_bfloat16 Ksm[2][64*KS];
    __shared__ __align__(16) __nv_bfloat16 Vsm[2][64*KS];

    int qt = blockIdx.x, h = blockIdx.y, b = blockIdx.z;
    int kvh = h / 3;
    int tid = threadIdx.x;
    int w = tid >> 5, lane = tid & 31;
    int g = lane >> 2, t = lane & 3;
    int lr = lane & 7, lb1 = (lane >> 3) & 1, lb2 = lane >> 4;
    int q0  = qt * 128;
    int qr0 = w * 16;
    bool is_exp = (qt == 16);
    int nkt = is_exp ? 33 : 32;

    // per-thread KV load coords (hoisted): 2 chunks per array
    int key0 = tid >> 3,        seg0 = (tid & 7);
    int key1 = (tid+256) >> 3,  seg1 = ((tid+256) & 7);
    const __nv_bfloat16* k_src0 = g_k + ((size_t)(b*LT + key0))*NKV + kvh*HD_ + seg0*8;
    const __nv_bfloat16* k_src1 = g_k + ((size_t)(b*LT + key1))*NKV + kvh*HD_ + seg1*8;
    const __nv_bfloat16* v_src0 = g_v + ((size_t)(b*LT + key0))*NKV + kvh*HD_ + seg0*8;
    const __nv_bfloat16* v_src1 = g_v + ((size_t)(b*LT + key1))*NKV + kvh*HD_ + seg1*8;

    // Q fragments (pre-scaled by rope): 4 k16-steps x 4 pair regs
    uint32_t qa[4][4];
    {
        int r0 = q0 + qr0 + g;     if (r0 > LT-1) r0 = LT-1;
        int r1 = q0 + qr0 + g + 8; if (r1 > LT-1) r1 = LT-1;
        const __nv_bfloat16* p0 = g_q + ((size_t)(b*LT + r0))*D_ + h*HD_;
        const __nv_bfloat16* p1 = g_q + ((size_t)(b*LT + r1))*D_ + h*HD_;
        #pragma unroll
        for (int ks = 0; ks < 4; ks++) {
            int kb = ks*16;
            qa[ks][0] = *(const uint32_t*)(p0 + kb + 2*t);
            qa[ks][1] = *(const uint32_t*)(p1 + kb + 2*t);
            qa[ks][2] = *(const uint32_t*)(p0 + kb + 2*t + 8);
            qa[ks][3] = *(const uint32_t*)(p1 + kb + 2*t + 8);
        }
    }

    float o[8][4] = {};
    float m2[2] = {-1e30f, -1e30f};
    float l2[2] = {0.f, 0.f};

    // prologue: prefetch kv-tile 0 (K group, then V group)
    {
        cp16(&Ksm[0][key0*KS + seg0*8], k_src0);
        cp16(&Ksm[0][key1*KS + seg1*8], k_src1);
        cp_commit();
        cp16(&Vsm[0][key0*KS + seg0*8], v_src0);
        cp16(&Vsm[0][key1*KS + seg1*8], v_src1);
        cp_commit();
    }

    for (int kt = 0; kt < nkt; kt++) {
        int buf = kt & 1;
        // wait K(kt) only (V(kt) may still be in flight)
        cp_wait1();
        __syncthreads();   // K(kt) visible block-wide; all warps done with buf^1
        bool pf = (kt + 1 < nkt);
        if (pf) {
            size_t off = (size_t)(kt+1)*64*NKV;
            cp16(&Ksm[buf^1][key0*KS + seg0*8], k_src0 + off);
            cp16(&Ksm[buf^1][key1*KS + seg1*8], k_src1 + off);
            cp_commit();
            cp16(&Vsm[buf^1][key0*KS + seg0*8], v_src0 + off);
            cp16(&Vsm[buf^1][key1*KS + seg1*8], v_src1 + off);
            cp_commit();
        }

        // S = Q K^T (16q x 64k per warp); scores in log2 units
        float sacc[8][4] = {};
        #pragma unroll
        for (int ks = 0; ks < 4; ks++) {
            int kb = ks*16;
            #pragma unroll
            for (int ntp = 0; ntp < 4; ntp++) {
                uint32_t bq[4];
                ldsm4(bq, &Ksm[buf][(ntp*16 + lr + lb2*8)*KS + kb + lb1*8]);
                mma16(sacc[2*ntp  ], qa[ks], bq[0], bq[1]);
                mma16(sacc[2*ntp+1], qa[ks], bq[2], bq[3]);
            }
        }
        // causal mask in expert/expert block
        if (is_exp && kt == 32) {
            int qe0 = qr0 + g, qe1 = qe0 + 8;
            #pragma unroll
            for (int nt = 0; nt < 8; nt++) {
                int c0 = nt*8 + 2*t, c1 = c0 + 1;
                if (c0 > qe0) sacc[nt][0] = -1e30f;
                if (c1 > qe0) sacc[nt][1] = -1e30f;
                if (c0 > qe1) sacc[nt][2] = -1e30f;
                if (c1 > qe1) sacc[nt][3] = -1e30f;
            }
        }
        // online softmax per row-half (rows g and g+8), log2 space (no smem)
        #pragma unroll
        for (int hh = 0; hh < 2; hh++) {
            float rm = -1e30f;
            #pragma unroll
            for (int nt = 0; nt < 8; nt++)
                rm = fmaxf(rm, fmaxf(sacc[nt][hh*2], sacc[nt][hh*2+1]));
            rm = fmaxf(rm, __shfl_xor_sync(0xffffffffu, rm, 1));
            rm = fmaxf(rm, __shfl_xor_sync(0xffffffffu, rm, 2));
            float mn = fmaxf(m2[hh], rm);
            float alpha = exp2f(m2[hh] - mn);
            float sum = 0.f;
            #pragma unroll
            for (int nt = 0; nt < 8; nt++) {
                float p0 = exp2f(sacc[nt][hh*2  ] - mn);
                float p1 = exp2f(sacc[nt][hh*2+1] - mn);
                sacc[nt][hh*2] = p0; sacc[nt][hh*2+1] = p1;
                sum += p0 + p1;
            }
            sum += __shfl_xor_sync(0xffffffffu, sum, 1);
            sum += __shfl_xor_sync(0xffffffffu, sum, 2);
            l2[hh] = l2[hh]*alpha + sum;
            m2[hh] = mn;
            #pragma unroll
            for (int nt = 0; nt < 8; nt++) {
                o[nt][hh*2]   *= alpha;
                o[nt][hh*2+1] *= alpha;
            }
        }
        // now require V(kt): pending after prefetch = {V(kt),K(kt+1),V(kt+1)}
        if (pf) cp_wait2(); else cp_wait0();
        __syncthreads();   // V(kt) visible block-wide
        // O += P V (P A-frag packed straight from S C-frag; V via LDSM.trans)
        #pragma unroll
        for (int ks = 0; ks < 4; ks++) {
            int kb = ks*16;
            uint32_t pa[4];
            pa[0] = pack2(sacc[2*ks  ][0], sacc[2*ks  ][1]);
            pa[1] = pack2(sacc[2*ks  ][2], sacc[2*ks  ][3]);
            pa[2] = pack2(sacc[2*ks+1][0], sacc[2*ks+1][1]);
            pa[3] = pack2(sacc[2*ks+1][2], sacc[2*ks+1][3]);
            #pragma unroll
            for (int ntp = 0; ntp < 4; ntp++) {
                uint32_t bq[4];
                ldsm4t(bq, &Vsm[buf][(kb + lr + lb1*8)*KS + ntp*16 + lb2*8]);
                mma16(o[2*ntp  ], pa, bq[0], bq[1]);
                mma16(o[2*ntp+1], pa, bq[2], bq[3]);
            }
        }
    }

    // normalize + store bf16
    float inv0 = 1.0f / l2[0];
    float inv1 = 1.0f / l2[1];
    int r0 = q0 + qr0 + g;
    int r1 = r0 + 8;
    #pragma unroll
    for (int nt = 0; nt < 8; nt++) {
        int col = h*HD_ + nt*8 + 2*t;
        if (r0 < LT)
            *(uint32_t*)&g_at[((size_t)(b*LT + r0))*D_ + col] =
                pack2(o[nt][0]*inv0, o[nt][1]*inv0);
        if (r1 < LT)
            *(uint32_t*)&g_at[((size_t)(b*LT + r1))*D_ + col] =
                pack2(o[nt][2]*inv1, o[nt][3]*inv1);
    }
}

// ---------------------------------------------------------------------------
// kernel_launch: ONLY kernel launches (graph-capture friendly).
// ---------------------------------------------------------------------------
extern "C" void kernel_launch(void* const* d_in, const int* in_sizes, int n_in,
                              void* d_out, int out_size)
{
    const float* hv   = (const float*)d_in[0];
    const float* he   = (const float*)d_in[1];
    const float* lnv  = (const float*)d_in[2];
    const float* wq_v = (const float*)d_in[3];
    const float* wk_v = (const float*)d_in[4];
    const float* wv_v = (const float*)d_in[5];
    const float* wo_v = (const float*)d_in[6];
    const float* lne  = (const float*)d_in[7];
    const float* wq_e = (const float*)d_in[8];
    const float* wk_e = (const float*)d_in[9];
    const float* wv_e = (const float*)d_in[10];
    const float* wo_e = (const float*)d_in[11];
    const int*   posv = (const int*)d_in[12];
    const int*   pose = (const int*)d_in[13];
    float* out = (float*)d_out;

    // fused weight-convert + rmsnorm
    prep_kernel<<<7200 + B_*LT, 256>>>(hv, he, lnv, lne,
        wq_v, wk_v, wv_v, wo_v, wq_e, wk_e, wv_e, wo_e);

    // fused QKV projection, both streams
    fgemm<0><<<dim3(25,17,4), 256>>>(nullptr, nullptr, nullptr);

    // rope v2: one warp per row
    rope_kernel<<<(B_*LT)/8, 256>>>(posv, pose);

    attn_tc<<<dim3(17,15,4), 256>>>();

    // fused output projection + residual, both streams
    fgemm<1><<<dim3(15,17,4), 256>>>(out, hv, he);
}